// round 3
// baseline (speedup 1.0000x reference)
#include <cuda_runtime.h>
#include <math_constants.h>

// ---------------- scratch (static __device__, no allocation) ----------------
#define MAXN (16384)
#define MAXC (256)
#define MAXM (2048)

__device__ float  g_prob[MAXN * MAXC];   // softmax probabilities [N, nc]
__device__ float4 g_pext[MAXN * 4];      // per-pred:  {pmin,volp},{pmax,_},{box0-3},{box4,box5,_,_}
__device__ float4 g_text[MAXM * 4];      // per-tgt:   {tmin,volt},{tmax,label},{box0-3},{box4,box5,_,_}
__device__ int    g_lab64;               // 1 if tgt_labels is int64, else 0

#define EPS 1e-6f

// ---------------- kernel 0: sniff label dtype ----------------
__global__ void sniff_labels_kernel(const unsigned int* __restrict__ lab, int M) {
    if (threadIdx.x == 0 && blockIdx.x == 0) {
        int n = M / 2; if (n > 64) n = 64;
        int is64 = (n > 0) ? 1 : 0;
        for (int j = 0; j < n; j++) {
            if (lab[2 * j + 1] != 0u) { is64 = 0; break; }
        }
        g_lab64 = is64;
    }
}

// ---------------- kernel 1: row softmax (one warp per row) ----------------
__global__ void softmax_kernel(const float* __restrict__ logits, int N, int nc) {
    int gwarp = (blockIdx.x * blockDim.x + threadIdx.x) >> 5;
    int lane  = threadIdx.x & 31;
    if (gwarp >= N) return;
    const float* row = logits + (size_t)gwarp * nc;

    float mx = -CUDART_INF_F;
    for (int c = lane; c < nc; c += 32) mx = fmaxf(mx, __ldg(&row[c]));
    #pragma unroll
    for (int o = 16; o > 0; o >>= 1) mx = fmaxf(mx, __shfl_xor_sync(0xffffffffu, mx, o));

    if (nc <= 256) {
        float ev[8];
        float s = 0.f;
        #pragma unroll
        for (int k = 0; k < 8; k++) {
            int c = lane + k * 32;
            float e = (c < nc) ? __expf(__ldg(&row[c]) - mx) : 0.f;
            ev[k] = e;
            s += e;
        }
        #pragma unroll
        for (int o = 16; o > 0; o >>= 1) s += __shfl_xor_sync(0xffffffffu, s, o);
        float r = __fdividef(1.f, s);
        #pragma unroll
        for (int k = 0; k < 8; k++) {
            int c = lane + k * 32;
            if (c < nc) g_prob[(size_t)gwarp * nc + c] = ev[k] * r;
        }
    } else {
        float s = 0.f;
        for (int c = lane; c < nc; c += 32) s += __expf(__ldg(&row[c]) - mx);
        #pragma unroll
        for (int o = 16; o > 0; o >>= 1) s += __shfl_xor_sync(0xffffffffu, s, o);
        float r = __fdividef(1.f, s);
        for (int c = lane; c < nc; c += 32)
            g_prob[(size_t)gwarp * nc + c] = __expf(__ldg(&row[c]) - mx) * r;
    }
}

// ---------------- kernel 2: box extents (one thread per box) ----------------
// which == 0 -> write g_pext (preds, labels==nullptr)
// which == 1 -> write g_text (targets, labels valid)
__global__ void ext_kernel(const float* __restrict__ boxes,
                           const float* __restrict__ corners,
                           const void*  __restrict__ labels,
                           int which, int count) {
    int i = blockIdx.x * blockDim.x + threadIdx.x;
    if (i >= count) return;

    // resolve the device symbol INSIDE device code (never pass from host!)
    float4* ext = which ? g_text : g_pext;

    const float4* c4 = (const float4*)(corners + (size_t)i * 24);
    float v[24];
    #pragma unroll
    for (int k = 0; k < 6; k++) {
        float4 t = __ldg(&c4[k]);
        v[4*k+0] = t.x; v[4*k+1] = t.y; v[4*k+2] = t.z; v[4*k+3] = t.w;
    }
    float mnx = v[0], mny = v[1], mnz = v[2];
    float mxx = v[0], mxy = v[1], mxz = v[2];
    #pragma unroll
    for (int j = 1; j < 8; j++) {
        mnx = fminf(mnx, v[3*j+0]);  mxx = fmaxf(mxx, v[3*j+0]);
        mny = fminf(mny, v[3*j+1]);  mxy = fmaxf(mxy, v[3*j+1]);
        mnz = fminf(mnz, v[3*j+2]);  mxz = fmaxf(mxz, v[3*j+2]);
    }
    float vol = (mxx - mnx) * (mxy - mny) * (mxz - mnz);
    const float* b = boxes + (size_t)i * 6;
    float lab = 0.f;
    if (labels) {
        int li;
        if (g_lab64) li = (int)__ldg(&((const long long*)labels)[i]);
        else         li = __ldg(&((const int*)labels)[i]);
        lab = __int_as_float(li);
    }

    ext[i*4+0] = make_float4(mnx, mny, mnz, vol);
    ext[i*4+1] = make_float4(mxx, mxy, mxz, lab);
    ext[i*4+2] = make_float4(__ldg(&b[0]), __ldg(&b[1]), __ldg(&b[2]), __ldg(&b[3]));
    ext[i*4+3] = make_float4(__ldg(&b[4]), __ldg(&b[5]), 0.f, 0.f);
}

// ---------------- kernel 3: pairwise cost ----------------
#define TILE_N 16
#define BLOCK_M 256

__global__ __launch_bounds__(BLOCK_M)
void cost_kernel(float* __restrict__ out, int N, int M, int nc) {
    int m = blockIdx.x * BLOCK_M + threadIdx.x;
    if (m >= M) return;

    float4 t0 = g_text[m*4+0];   // tmin, volt
    float4 t1 = g_text[m*4+1];   // tmax, label bits
    float4 t2 = g_text[m*4+2];   // tbox 0..3
    float4 t3 = g_text[m*4+3];   // tbox 4..5
    int label = __float_as_int(t1.w);
    const float* probL = g_prob + label;

    int n0 = blockIdx.y * TILE_N;
    int nend = min(TILE_N, N - n0);

    #pragma unroll 4
    for (int i = 0; i < nend; i++) {
        int n = n0 + i;
        float4 p0 = __ldg(&g_pext[n*4+0]);
        float4 p1 = __ldg(&g_pext[n*4+1]);
        float4 p2 = __ldg(&g_pext[n*4+2]);
        float4 p3 = __ldg(&g_pext[n*4+3]);
        float  pc = __ldg(&probL[(size_t)n * nc]);

        float lox = fmaxf(p0.x, t0.x), loy = fmaxf(p0.y, t0.y), loz = fmaxf(p0.z, t0.z);
        float hix = fminf(p1.x, t1.x), hiy = fminf(p1.y, t1.y), hiz = fminf(p1.z, t1.z);
        float dx = fmaxf(hix - lox, 0.f);
        float dy = fmaxf(hiy - loy, 0.f);
        float dz = fmaxf(hiz - loz, 0.f);
        float inter = dx * dy * dz;

        float uni = p0.w + t0.w - inter;

        float elx = fminf(p0.x, t0.x), ely = fminf(p0.y, t0.y), elz = fminf(p0.z, t0.z);
        float ehx = fmaxf(p1.x, t1.x), ehy = fmaxf(p1.y, t1.y), ehz = fmaxf(p1.z, t1.z);
        float enc = (ehx - elx) * (ehy - ely) * (ehz - elz);

        float giou = __fdividef(inter, uni + EPS) - __fdividef(enc - uni, enc + EPS);

        float bb = fabsf(p2.x - t2.x) + fabsf(p2.y - t2.y)
                 + fabsf(p2.z - t2.z) + fabsf(p2.w - t2.w)
                 + fabsf(p3.x - t3.x) + fabsf(p3.y - t3.y);

        out[(size_t)n * M + m] = bb - pc - giou;
    }
}

// ---------------- launch ----------------
extern "C" void kernel_launch(void* const* d_in, const int* in_sizes, int n_in,
                              void* d_out, int out_size) {
    // ---- identify inputs by element count (order-proof) ----
    int iLab = 0;
    for (int i = 1; i < n_in; i++)
        if (in_sizes[i] < in_sizes[iLab]) iLab = i;
    long long M = in_sizes[iLab];

    int iTB = -1, iTC = -1;
    for (int i = 0; i < n_in; i++) {
        if (i == iLab) continue;
        if (in_sizes[i] == 6  * M) iTB = i;
        if (in_sizes[i] == 24 * M) iTC = i;
    }
    int rem[3], r = 0;
    for (int i = 0; i < n_in; i++)
        if (i != iLab && i != iTB && i != iTC) rem[r++] = i;
    int iPB = -1, iPC = -1, iLg = -1;
    for (int a = 0; a < 3; a++) {
        for (int b = 0; b < 3; b++) {
            if (a != b && (long long)in_sizes[rem[b]] == 4LL * in_sizes[rem[a]]) {
                iPB = rem[a]; iPC = rem[b];
            }
        }
    }
    for (int a = 0; a < 3; a++)
        if (rem[a] != iPB && rem[a] != iPC) iLg = rem[a];

    const float* pred_logits  = (const float*)d_in[iLg];
    const float* pred_boxes   = (const float*)d_in[iPB];
    const float* pred_corners = (const float*)d_in[iPC];
    const void*  tgt_labels   =               d_in[iLab];
    const float* tgt_boxes    = (const float*)d_in[iTB];
    const float* tgt_corners  = (const float*)d_in[iTC];
    float* out = (float*)d_out;

    int N  = in_sizes[iPB] / 6;
    int nc = (int)((long long)in_sizes[iLg] / N);
    int Mi = (int)M;

    // kernel 0: sniff label dtype
    sniff_labels_kernel<<<1, 32>>>((const unsigned int*)tgt_labels, Mi);

    // kernel 1: softmax, one warp per row
    {
        int warps_per_block = 8;
        int blocks = (N + warps_per_block - 1) / warps_per_block;
        softmax_kernel<<<blocks, warps_per_block * 32>>>(pred_logits, N, nc);
    }
    // kernel 2: extents for preds and targets (destination chosen inside kernel)
    {
        ext_kernel<<<(N + 255) / 256, 256>>>(pred_boxes, pred_corners, nullptr, 0, N);
        ext_kernel<<<(Mi + 255) / 256, 256>>>(tgt_boxes, tgt_corners, tgt_labels, 1, Mi);
    }
    // kernel 3: pairwise cost
    {
        dim3 grid((Mi + BLOCK_M - 1) / BLOCK_M, (N + TILE_N - 1) / TILE_N);
        cost_kernel<<<grid, BLOCK_M>>>(out, N, Mi, nc);
    }
}

// round 4
// speedup vs baseline: 1.0629x; 1.0629x over previous
#include <cuda_runtime.h>
#include <math_constants.h>

// ---------------- scratch (static __device__, no allocation) ----------------
#define MAXN (16384)
#define MAXC (256)
#define MAXM (2048)

__device__ float  g_prob[MAXN * MAXC];   // softmax probabilities [N, nc]
__device__ float4 g_pext[MAXN * 4];      // per-pred:  {pmin,volp},{pmax,_},{box0-3},{box4,box5,_,_}
__device__ float4 g_text[MAXM * 4];      // per-tgt:   {tmin,volt},{tmax,label},{box0-3},{box4,box5,_,_}

#define EPS 1e-6f

// ---------------- kernel 1: row softmax (one warp per row) ----------------
__global__ void softmax_kernel(const float* __restrict__ logits, int N, int nc) {
    int gwarp = (blockIdx.x * blockDim.x + threadIdx.x) >> 5;
    int lane  = threadIdx.x & 31;
    if (gwarp >= N) return;
    const float* row = logits + (size_t)gwarp * nc;

    float mx = -CUDART_INF_F;
    for (int c = lane; c < nc; c += 32) mx = fmaxf(mx, __ldg(&row[c]));
    #pragma unroll
    for (int o = 16; o > 0; o >>= 1) mx = fmaxf(mx, __shfl_xor_sync(0xffffffffu, mx, o));

    if (nc <= 256) {
        float ev[8];
        float s = 0.f;
        #pragma unroll
        for (int k = 0; k < 8; k++) {
            int c = lane + k * 32;
            float e = (c < nc) ? __expf(__ldg(&row[c]) - mx) : 0.f;
            ev[k] = e;
            s += e;
        }
        #pragma unroll
        for (int o = 16; o > 0; o >>= 1) s += __shfl_xor_sync(0xffffffffu, s, o);
        float r = __fdividef(1.f, s);
        #pragma unroll
        for (int k = 0; k < 8; k++) {
            int c = lane + k * 32;
            if (c < nc) g_prob[(size_t)gwarp * nc + c] = ev[k] * r;
        }
    } else {
        float s = 0.f;
        for (int c = lane; c < nc; c += 32) s += __expf(__ldg(&row[c]) - mx);
        #pragma unroll
        for (int o = 16; o > 0; o >>= 1) s += __shfl_xor_sync(0xffffffffu, s, o);
        float r = __fdividef(1.f, s);
        for (int c = lane; c < nc; c += 32)
            g_prob[(size_t)gwarp * nc + c] = __expf(__ldg(&row[c]) - mx) * r;
    }
}

// ---------------- kernel 2: merged extents (preds [0,N) + targets [N,N+M)) ---
// Label dtype (int32 vs int64) is detected block-locally: the first 64 threads
// of each block check the int64-view hi-words (bytes touched <= 512, always
// in-bounds for M >= 64 since even int32 labels occupy 4*M >= 512 bytes for
// M >= 128; for smaller M we check fewer entries).
__global__ void ext_kernel(const float* __restrict__ pboxes,
                           const float* __restrict__ pcorners,
                           const float* __restrict__ tboxes,
                           const float* __restrict__ tcorners,
                           const void*  __restrict__ labels,
                           int N, int M) {
    __shared__ int sh_hi_nonzero;
    if (threadIdx.x == 0) sh_hi_nonzero = 0;
    __syncthreads();

    // parallel dtype check (cheap; all blocks do it)
    {
        int nchk = M / 2; if (nchk > 64) nchk = 64;
        int j = threadIdx.x;
        if (j < nchk) {
            unsigned int hi = __ldg(&((const unsigned int*)labels)[2 * j + 1]);
            if (hi != 0u) sh_hi_nonzero = 1;
        }
    }
    __syncthreads();
    int is64 = (sh_hi_nonzero == 0);

    int i = blockIdx.x * blockDim.x + threadIdx.x;
    if (i >= N + M) return;

    int  isT = (i >= N);
    int  idx = isT ? (i - N) : i;
    const float* boxes   = isT ? tboxes   : pboxes;
    const float* corners = isT ? tcorners : pcorners;
    float4* ext = isT ? g_text : g_pext;   // device symbols resolved in device code

    const float4* c4 = (const float4*)(corners + (size_t)idx * 24);
    float v[24];
    #pragma unroll
    for (int k = 0; k < 6; k++) {
        float4 t = __ldg(&c4[k]);
        v[4*k+0] = t.x; v[4*k+1] = t.y; v[4*k+2] = t.z; v[4*k+3] = t.w;
    }
    float mnx = v[0], mny = v[1], mnz = v[2];
    float mxx = v[0], mxy = v[1], mxz = v[2];
    #pragma unroll
    for (int j = 1; j < 8; j++) {
        mnx = fminf(mnx, v[3*j+0]);  mxx = fmaxf(mxx, v[3*j+0]);
        mny = fminf(mny, v[3*j+1]);  mxy = fmaxf(mxy, v[3*j+1]);
        mnz = fminf(mnz, v[3*j+2]);  mxz = fmaxf(mxz, v[3*j+2]);
    }
    float vol = (mxx - mnx) * (mxy - mny) * (mxz - mnz);
    const float* b = boxes + (size_t)idx * 6;

    float lab = 0.f;
    if (isT) {
        int li;
        if (is64) li = (int)__ldg(&((const long long*)labels)[idx]);
        else      li = __ldg(&((const int*)labels)[idx]);
        lab = __int_as_float(li);
    }

    ext[idx*4+0] = make_float4(mnx, mny, mnz, vol);
    ext[idx*4+1] = make_float4(mxx, mxy, mxz, lab);
    ext[idx*4+2] = make_float4(__ldg(&b[0]), __ldg(&b[1]), __ldg(&b[2]), __ldg(&b[3]));
    ext[idx*4+3] = make_float4(__ldg(&b[4]), __ldg(&b[5]), 0.f, 0.f);
}

// ---------------- kernel 3: pairwise cost (2 targets per thread) -------------
#define TILE_N 16
#define TPB 128

__device__ __forceinline__ float pair_cost(
    const float4& p0, const float4& p1, const float4& p2, const float4& p3,
    float pc,
    const float4& t0, const float4& t1, const float4& t2, const float4& t3)
{
    float lox = fmaxf(p0.x, t0.x), loy = fmaxf(p0.y, t0.y), loz = fmaxf(p0.z, t0.z);
    float hix = fminf(p1.x, t1.x), hiy = fminf(p1.y, t1.y), hiz = fminf(p1.z, t1.z);
    float dx = fmaxf(hix - lox, 0.f);
    float dy = fmaxf(hiy - loy, 0.f);
    float dz = fmaxf(hiz - loz, 0.f);
    float inter = dx * dy * dz;

    float uni = p0.w + t0.w - inter;

    float elx = fminf(p0.x, t0.x), ely = fminf(p0.y, t0.y), elz = fminf(p0.z, t0.z);
    float ehx = fmaxf(p1.x, t1.x), ehy = fmaxf(p1.y, t1.y), ehz = fmaxf(p1.z, t1.z);
    float enc = (ehx - elx) * (ehy - ely) * (ehz - elz);

    float giou = __fdividef(inter, uni + EPS) - __fdividef(enc - uni, enc + EPS);

    float bb = fabsf(p2.x - t2.x) + fabsf(p2.y - t2.y)
             + fabsf(p2.z - t2.z) + fabsf(p2.w - t2.w)
             + fabsf(p3.x - t3.x) + fabsf(p3.y - t3.y);

    return bb - pc - giou;
}

__global__ __launch_bounds__(TPB)
void cost_kernel(float* __restrict__ out, int N, int M, int nc) {
    int m0 = (blockIdx.x * TPB + threadIdx.x) * 2;
    if (m0 >= M) return;
    bool has2 = (m0 + 1 < M);
    int  m1 = has2 ? m0 + 1 : m0;

    // per-target registers, live across all TILE_N iterations
    float4 a0 = g_text[m0*4+0], a1 = g_text[m0*4+1], a2 = g_text[m0*4+2], a3 = g_text[m0*4+3];
    float4 b0 = g_text[m1*4+0], b1 = g_text[m1*4+1], b2 = g_text[m1*4+2], b3 = g_text[m1*4+3];
    const float* probA = g_prob + __float_as_int(a1.w);
    const float* probB = g_prob + __float_as_int(b1.w);

    int n0 = blockIdx.y * TILE_N;
    int nend = min(TILE_N, N - n0);

    #pragma unroll 4
    for (int i = 0; i < nend; i++) {
        int n = n0 + i;
        float4 p0 = __ldg(&g_pext[n*4+0]);
        float4 p1 = __ldg(&g_pext[n*4+1]);
        float4 p2 = __ldg(&g_pext[n*4+2]);
        float4 p3 = __ldg(&g_pext[n*4+3]);
        size_t roff = (size_t)n * nc;
        float pcA = __ldg(&probA[roff]);
        float pcB = __ldg(&probB[roff]);

        float cA = pair_cost(p0, p1, p2, p3, pcA, a0, a1, a2, a3);
        float cB = pair_cost(p0, p1, p2, p3, pcB, b0, b1, b2, b3);

        if (has2) {
            *(float2*)(out + (size_t)n * M + m0) = make_float2(cA, cB);
        } else {
            out[(size_t)n * M + m0] = cA;
        }
    }
}

// ---------------- launch ----------------
extern "C" void kernel_launch(void* const* d_in, const int* in_sizes, int n_in,
                              void* d_out, int out_size) {
    // ---- identify inputs by element count (order-proof) ----
    int iLab = 0;
    for (int i = 1; i < n_in; i++)
        if (in_sizes[i] < in_sizes[iLab]) iLab = i;
    long long M = in_sizes[iLab];

    int iTB = -1, iTC = -1;
    for (int i = 0; i < n_in; i++) {
        if (i == iLab) continue;
        if (in_sizes[i] == 6  * M) iTB = i;
        if (in_sizes[i] == 24 * M) iTC = i;
    }
    int rem[3], r = 0;
    for (int i = 0; i < n_in; i++)
        if (i != iLab && i != iTB && i != iTC) rem[r++] = i;
    int iPB = -1, iPC = -1, iLg = -1;
    for (int a = 0; a < 3; a++) {
        for (int b = 0; b < 3; b++) {
            if (a != b && (long long)in_sizes[rem[b]] == 4LL * in_sizes[rem[a]]) {
                iPB = rem[a]; iPC = rem[b];
            }
        }
    }
    for (int a = 0; a < 3; a++)
        if (rem[a] != iPB && rem[a] != iPC) iLg = rem[a];

    const float* pred_logits  = (const float*)d_in[iLg];
    const float* pred_boxes   = (const float*)d_in[iPB];
    const float* pred_corners = (const float*)d_in[iPC];
    const void*  tgt_labels   =               d_in[iLab];
    const float* tgt_boxes    = (const float*)d_in[iTB];
    const float* tgt_corners  = (const float*)d_in[iTC];
    float* out = (float*)d_out;

    int N  = in_sizes[iPB] / 6;
    int nc = (int)((long long)in_sizes[iLg] / N);
    int Mi = (int)M;

    // launch 1: softmax (one warp per row)
    {
        int warps_per_block = 8;
        int blocks = (N + warps_per_block - 1) / warps_per_block;
        softmax_kernel<<<blocks, warps_per_block * 32>>>(pred_logits, N, nc);
    }
    // launch 2: merged extents (preds + targets, label dtype detected in-block)
    {
        int total = N + Mi;
        ext_kernel<<<(total + 255) / 256, 256>>>(pred_boxes, pred_corners,
                                                 tgt_boxes, tgt_corners,
                                                 tgt_labels, N, Mi);
    }
    // launch 3: pairwise cost (2 m per thread)
    {
        int mthreads = (Mi + 1) / 2;
        dim3 grid((mthreads + TPB - 1) / TPB, (N + TILE_N - 1) / TILE_N);
        cost_kernel<<<grid, TPB>>>(out, N, Mi, nc);
    }
}

// round 5
// speedup vs baseline: 1.1336x; 1.0666x over previous
#include <cuda_runtime.h>
#include <math_constants.h>

// ---------------- scratch (static __device__, no allocation) ----------------
#define MAXN (16384)
#define MAXC (256)
#define MAXM (2048)

__device__ float  g_prob[MAXN * MAXC];   // softmax probabilities [N, nc]
__device__ float4 g_pext[MAXN * 4];      // per-pred:  {pmin,volp},{pmax,_},{box0-3},{box4,box5,_,_}
__device__ float4 g_text[MAXM * 4];      // per-tgt:   {tmin,volt},{tmax,label},{box0-3},{box4,box5,_,_}

#define EPS 1e-6f

// =============== kernel 1: fused prep (ext blocks + softmax blocks) =========
// blocks [0, EB)        : extents for preds [0,N) and targets [N,N+M)
// blocks [EB, EB+SB)    : softmax, 8 warps/block, 1 row/warp
__global__ __launch_bounds__(256)
void prep_kernel(const float* __restrict__ logits,
                 const float* __restrict__ pboxes,
                 const float* __restrict__ pcorners,
                 const float* __restrict__ tboxes,
                 const float* __restrict__ tcorners,
                 const void*  __restrict__ labels,
                 int N, int M, int nc, int EB) {
    if ((int)blockIdx.x < EB) {
        // ---------------- extents path ----------------
        __shared__ int sh_hi_nonzero;
        if (threadIdx.x == 0) sh_hi_nonzero = 0;
        __syncthreads();
        {
            int nchk = M / 2; if (nchk > 64) nchk = 64;
            int j = threadIdx.x;
            if (j < nchk) {
                unsigned int hi = __ldg(&((const unsigned int*)labels)[2 * j + 1]);
                if (hi != 0u) sh_hi_nonzero = 1;
            }
        }
        __syncthreads();
        int is64 = (sh_hi_nonzero == 0);

        int i = blockIdx.x * blockDim.x + threadIdx.x;
        if (i >= N + M) return;

        int  isT = (i >= N);
        int  idx = isT ? (i - N) : i;
        const float* boxes   = isT ? tboxes   : pboxes;
        const float* corners = isT ? tcorners : pcorners;
        float4* ext = isT ? g_text : g_pext;

        const float4* c4 = (const float4*)(corners + (size_t)idx * 24);
        float v[24];
        #pragma unroll
        for (int k = 0; k < 6; k++) {
            float4 t = __ldg(&c4[k]);
            v[4*k+0] = t.x; v[4*k+1] = t.y; v[4*k+2] = t.z; v[4*k+3] = t.w;
        }
        float mnx = v[0], mny = v[1], mnz = v[2];
        float mxx = v[0], mxy = v[1], mxz = v[2];
        #pragma unroll
        for (int j = 1; j < 8; j++) {
            mnx = fminf(mnx, v[3*j+0]);  mxx = fmaxf(mxx, v[3*j+0]);
            mny = fminf(mny, v[3*j+1]);  mxy = fmaxf(mxy, v[3*j+1]);
            mnz = fminf(mnz, v[3*j+2]);  mxz = fmaxf(mxz, v[3*j+2]);
        }
        float vol = (mxx - mnx) * (mxy - mny) * (mxz - mnz);
        const float* b = boxes + (size_t)idx * 6;

        float lab = 0.f;
        if (isT) {
            int li;
            if (is64) li = (int)__ldg(&((const long long*)labels)[idx]);
            else      li = __ldg(&((const int*)labels)[idx]);
            lab = __int_as_float(li);
        }

        ext[idx*4+0] = make_float4(mnx, mny, mnz, vol);
        ext[idx*4+1] = make_float4(mxx, mxy, mxz, lab);
        ext[idx*4+2] = make_float4(__ldg(&b[0]), __ldg(&b[1]), __ldg(&b[2]), __ldg(&b[3]));
        ext[idx*4+3] = make_float4(__ldg(&b[4]), __ldg(&b[5]), 0.f, 0.f);
        return;
    }

    // ---------------- softmax path (one warp per row) ----------------
    int rowid = ((int)blockIdx.x - EB) * 8 + ((int)threadIdx.x >> 5);
    int lane  = threadIdx.x & 31;
    if (rowid >= N) return;
    const float* row = logits + (size_t)rowid * nc;

    if ((nc & 3) == 0 && nc <= 1024) {
        // vectorized single-pass (registers hold the row slice)
        const float4* r4 = (const float4*)row;
        int VL = nc >> 2;                 // float4 count
        float4 v[8];
        int cnt = 0;
        float mx = -CUDART_INF_F;
        for (int j = lane; j < VL; j += 32) {
            float4 t = __ldg(&r4[j]);
            v[cnt++] = t;
            mx = fmaxf(mx, fmaxf(fmaxf(t.x, t.y), fmaxf(t.z, t.w)));
        }
        #pragma unroll
        for (int o = 16; o > 0; o >>= 1) mx = fmaxf(mx, __shfl_xor_sync(0xffffffffu, mx, o));

        float s = 0.f;
        for (int k = 0; k < cnt; k++) {
            v[k].x = __expf(v[k].x - mx);
            v[k].y = __expf(v[k].y - mx);
            v[k].z = __expf(v[k].z - mx);
            v[k].w = __expf(v[k].w - mx);
            s += v[k].x + v[k].y + v[k].z + v[k].w;
        }
        #pragma unroll
        for (int o = 16; o > 0; o >>= 1) s += __shfl_xor_sync(0xffffffffu, s, o);
        float r = __fdividef(1.f, s);

        float4* o4 = (float4*)(g_prob + (size_t)rowid * nc);
        cnt = 0;
        for (int j = lane; j < VL; j += 32) {
            float4 t = v[cnt++];
            t.x *= r; t.y *= r; t.z *= r; t.w *= r;
            o4[j] = t;
        }
    } else {
        // generic scalar fallback
        float mx = -CUDART_INF_F;
        for (int c = lane; c < nc; c += 32) mx = fmaxf(mx, __ldg(&row[c]));
        #pragma unroll
        for (int o = 16; o > 0; o >>= 1) mx = fmaxf(mx, __shfl_xor_sync(0xffffffffu, mx, o));
        float s = 0.f;
        for (int c = lane; c < nc; c += 32) s += __expf(__ldg(&row[c]) - mx);
        #pragma unroll
        for (int o = 16; o > 0; o >>= 1) s += __shfl_xor_sync(0xffffffffu, s, o);
        float r = __fdividef(1.f, s);
        for (int c = lane; c < nc; c += 32)
            g_prob[(size_t)rowid * nc + c] = __expf(__ldg(&row[c]) - mx) * r;
    }
}

// =============== kernel 2: pairwise cost =====================================
#define TPB_COST 256
#define TILE_N 16
#define MPT 4

__device__ __forceinline__ float pair_cost(
    const float4& p0, const float4& p1, const float4& p2, const float4& p3,
    float pc,
    const float4& t0, const float4& t1, const float4& t2, const float4& t3)
{
    float lox = fmaxf(p0.x, t0.x), loy = fmaxf(p0.y, t0.y), loz = fmaxf(p0.z, t0.z);
    float hix = fminf(p1.x, t1.x), hiy = fminf(p1.y, t1.y), hiz = fminf(p1.z, t1.z);
    float dx = fmaxf(hix - lox, 0.f);
    float dy = fmaxf(hiy - loy, 0.f);
    float dz = fmaxf(hiz - loz, 0.f);
    float inter = dx * dy * dz;

    float uni = p0.w + t0.w - inter;

    float elx = fminf(p0.x, t0.x), ely = fminf(p0.y, t0.y), elz = fminf(p0.z, t0.z);
    float ehx = fmaxf(p1.x, t1.x), ehy = fmaxf(p1.y, t1.y), ehz = fmaxf(p1.z, t1.z);
    float enc = (ehx - elx) * (ehy - ely) * (ehz - elz);

    float giou = __fdividef(inter, uni + EPS) - __fdividef(enc - uni, enc + EPS);

    float bb = fabsf(p2.x - t2.x) + fabsf(p2.y - t2.y)
             + fabsf(p2.z - t2.z) + fabsf(p2.w - t2.w)
             + fabsf(p3.x - t3.x) + fabsf(p3.y - t3.y);

    return bb - pc - giou;
}

__global__ __launch_bounds__(TPB_COST, 2)
void cost_kernel(float* __restrict__ out, int N, int M, int nc) {
    __shared__ float  sp[TILE_N * MAXC];    // staged prob rows
    __shared__ float4 spx[TILE_N * 4];      // staged pred ext rows

    int n0   = blockIdx.y * TILE_N;
    int nend = min(TILE_N, N - n0);
    int tid  = threadIdx.x;
    bool fits = (nc <= MAXC);

    if (fits) {
        int tot  = nend * nc;
        int tot4 = tot >> 2;
        const float4* src = (const float4*)(g_prob + (size_t)n0 * nc);
        for (int j = tid; j < tot4; j += TPB_COST)
            ((float4*)sp)[j] = __ldg(&src[j]);
        for (int j = (tot4 << 2) + tid; j < tot; j += TPB_COST)
            sp[j] = __ldg(&g_prob[(size_t)n0 * nc + j]);
    }
    for (int j = tid; j < nend * 4; j += TPB_COST)
        spx[j] = __ldg(&g_pext[(size_t)n0 * 4 + j]);
    __syncthreads();

    int m0 = (blockIdx.x * TPB_COST + tid) * MPT;
    if (m0 >= M) return;

    if (m0 + MPT <= M) {
        // full 4-target path
        float4 t0[MPT], t1[MPT], t2[MPT], t3[MPT];
        int    lab[MPT];
        #pragma unroll
        for (int k = 0; k < MPT; k++) {
            int m = m0 + k;
            t0[k] = g_text[m*4+0]; t1[k] = g_text[m*4+1];
            t2[k] = g_text[m*4+2]; t3[k] = g_text[m*4+3];
            lab[k] = __float_as_int(t1[k].w);
        }

        for (int i = 0; i < nend; i++) {
            float4 p0 = spx[i*4+0];
            float4 p1 = spx[i*4+1];
            float4 p2 = spx[i*4+2];
            float4 p3 = spx[i*4+3];
            const float* prow = fits ? (sp + i * nc)
                                     : (g_prob + (size_t)(n0 + i) * nc);
            float c[MPT];
            #pragma unroll
            for (int k = 0; k < MPT; k++) {
                float pc = fits ? prow[lab[k]] : __ldg(&prow[lab[k]]);
                c[k] = pair_cost(p0, p1, p2, p3, pc, t0[k], t1[k], t2[k], t3[k]);
            }
            *(float4*)(out + (size_t)(n0 + i) * M + m0) = make_float4(c[0], c[1], c[2], c[3]);
        }
    } else {
        // ragged tail: scalar per m
        for (int m = m0; m < M; m++) {
            float4 t0 = g_text[m*4+0], t1 = g_text[m*4+1];
            float4 t2 = g_text[m*4+2], t3 = g_text[m*4+3];
            int lab = __float_as_int(t1.w);
            for (int i = 0; i < nend; i++) {
                float4 p0 = spx[i*4+0], p1 = spx[i*4+1];
                float4 p2 = spx[i*4+2], p3 = spx[i*4+3];
                const float* prow = fits ? (sp + i * nc)
                                         : (g_prob + (size_t)(n0 + i) * nc);
                float pc = fits ? prow[lab] : __ldg(&prow[lab]);
                out[(size_t)(n0 + i) * M + m] =
                    pair_cost(p0, p1, p2, p3, pc, t0, t1, t2, t3);
            }
        }
    }
}

// ---------------- launch ----------------
extern "C" void kernel_launch(void* const* d_in, const int* in_sizes, int n_in,
                              void* d_out, int out_size) {
    // ---- identify inputs by element count (order-proof) ----
    int iLab = 0;
    for (int i = 1; i < n_in; i++)
        if (in_sizes[i] < in_sizes[iLab]) iLab = i;
    long long M = in_sizes[iLab];

    int iTB = -1, iTC = -1;
    for (int i = 0; i < n_in; i++) {
        if (i == iLab) continue;
        if (in_sizes[i] == 6  * M) iTB = i;
        if (in_sizes[i] == 24 * M) iTC = i;
    }
    int rem[3], r = 0;
    for (int i = 0; i < n_in; i++)
        if (i != iLab && i != iTB && i != iTC) rem[r++] = i;
    int iPB = -1, iPC = -1, iLg = -1;
    for (int a = 0; a < 3; a++) {
        for (int b = 0; b < 3; b++) {
            if (a != b && (long long)in_sizes[rem[b]] == 4LL * in_sizes[rem[a]]) {
                iPB = rem[a]; iPC = rem[b];
            }
        }
    }
    for (int a = 0; a < 3; a++)
        if (rem[a] != iPB && rem[a] != iPC) iLg = rem[a];

    const float* pred_logits  = (const float*)d_in[iLg];
    const float* pred_boxes   = (const float*)d_in[iPB];
    const float* pred_corners = (const float*)d_in[iPC];
    const void*  tgt_labels   =               d_in[iLab];
    const float* tgt_boxes    = (const float*)d_in[iTB];
    const float* tgt_corners  = (const float*)d_in[iTC];
    float* out = (float*)d_out;

    int N  = in_sizes[iPB] / 6;
    int nc = (int)((long long)in_sizes[iLg] / N);
    int Mi = (int)M;

    // launch 1: fused prep (ext blocks first, then softmax blocks)
    {
        int EB = (N + Mi + 255) / 256;
        int SB = (N + 7) / 8;
        prep_kernel<<<EB + SB, 256>>>(pred_logits, pred_boxes, pred_corners,
                                      tgt_boxes, tgt_corners, tgt_labels,
                                      N, Mi, nc, EB);
    }
    // launch 2: pairwise cost
    {
        dim3 grid((Mi + TPB_COST * MPT - 1) / (TPB_COST * MPT),
                  (N + TILE_N - 1) / TILE_N);
        cost_kernel<<<grid, TPB_COST>>>(out, N, Mi, nc);
    }
}

// round 6
// speedup vs baseline: 1.1511x; 1.0155x over previous
#include <cuda_runtime.h>
#include <math_constants.h>

// ---------------- scratch (static __device__, no allocation) ----------------
#define MAXN (16384)
#define MAXC (256)
#define MAXM (2048)

__device__ float  g_prob[MAXN * MAXC];   // softmax probabilities [N, nc]
__device__ float4 g_pext[MAXN * 4];      // per-pred:  {pmin,volp},{pmax,_},{box0-3},{box4,box5,_,_}
__device__ float4 g_text[MAXM * 4];      // per-tgt:   {tmin,volt},{tmax,label},{box0-3},{box4,box5,_,_}

#define EPS 1e-6f

// =============== kernel 1: fused prep (ext blocks + softmax blocks) =========
__global__ __launch_bounds__(256)
void prep_kernel(const float* __restrict__ logits,
                 const float* __restrict__ pboxes,
                 const float* __restrict__ pcorners,
                 const float* __restrict__ tboxes,
                 const float* __restrict__ tcorners,
                 const void*  __restrict__ labels,
                 int N, int M, int nc, int EB) {
    if ((int)blockIdx.x < EB) {
        // ---------------- extents path ----------------
        __shared__ int sh_hi_nonzero;
        if (threadIdx.x == 0) sh_hi_nonzero = 0;
        __syncthreads();
        {
            int nchk = M / 2; if (nchk > 64) nchk = 64;
            int j = threadIdx.x;
            if (j < nchk) {
                unsigned int hi = __ldg(&((const unsigned int*)labels)[2 * j + 1]);
                if (hi != 0u) sh_hi_nonzero = 1;
            }
        }
        __syncthreads();
        int is64 = (sh_hi_nonzero == 0);

        int i = blockIdx.x * blockDim.x + threadIdx.x;
        if (i >= N + M) return;

        int  isT = (i >= N);
        int  idx = isT ? (i - N) : i;
        const float* boxes   = isT ? tboxes   : pboxes;
        const float* corners = isT ? tcorners : pcorners;
        float4* ext = isT ? g_text : g_pext;

        const float4* c4 = (const float4*)(corners + (size_t)idx * 24);
        float v[24];
        #pragma unroll
        for (int k = 0; k < 6; k++) {
            float4 t = __ldg(&c4[k]);
            v[4*k+0] = t.x; v[4*k+1] = t.y; v[4*k+2] = t.z; v[4*k+3] = t.w;
        }
        float mnx = v[0], mny = v[1], mnz = v[2];
        float mxx = v[0], mxy = v[1], mxz = v[2];
        #pragma unroll
        for (int j = 1; j < 8; j++) {
            mnx = fminf(mnx, v[3*j+0]);  mxx = fmaxf(mxx, v[3*j+0]);
            mny = fminf(mny, v[3*j+1]);  mxy = fmaxf(mxy, v[3*j+1]);
            mnz = fminf(mnz, v[3*j+2]);  mxz = fmaxf(mxz, v[3*j+2]);
        }
        float vol = (mxx - mnx) * (mxy - mny) * (mxz - mnz);
        const float* b = boxes + (size_t)idx * 6;

        float lab = 0.f;
        if (isT) {
            int li;
            if (is64) li = (int)__ldg(&((const long long*)labels)[idx]);
            else      li = __ldg(&((const int*)labels)[idx]);
            lab = __int_as_float(li);
        }

        ext[idx*4+0] = make_float4(mnx, mny, mnz, vol);
        ext[idx*4+1] = make_float4(mxx, mxy, mxz, lab);
        ext[idx*4+2] = make_float4(__ldg(&b[0]), __ldg(&b[1]), __ldg(&b[2]), __ldg(&b[3]));
        ext[idx*4+3] = make_float4(__ldg(&b[4]), __ldg(&b[5]), 0.f, 0.f);
        return;
    }

    // ---------------- softmax path (one warp per row) ----------------
    int rowid = ((int)blockIdx.x - EB) * 8 + ((int)threadIdx.x >> 5);
    int lane  = threadIdx.x & 31;
    if (rowid >= N) return;
    const float* row = logits + (size_t)rowid * nc;

    if ((nc & 3) == 0 && nc <= 1024) {
        const float4* r4 = (const float4*)row;
        int VL = nc >> 2;
        float4 v[8];
        int cnt = 0;
        float mx = -CUDART_INF_F;
        for (int j = lane; j < VL; j += 32) {
            float4 t = __ldg(&r4[j]);
            v[cnt++] = t;
            mx = fmaxf(mx, fmaxf(fmaxf(t.x, t.y), fmaxf(t.z, t.w)));
        }
        #pragma unroll
        for (int o = 16; o > 0; o >>= 1) mx = fmaxf(mx, __shfl_xor_sync(0xffffffffu, mx, o));

        float s = 0.f;
        for (int k = 0; k < cnt; k++) {
            v[k].x = __expf(v[k].x - mx);
            v[k].y = __expf(v[k].y - mx);
            v[k].z = __expf(v[k].z - mx);
            v[k].w = __expf(v[k].w - mx);
            s += v[k].x + v[k].y + v[k].z + v[k].w;
        }
        #pragma unroll
        for (int o = 16; o > 0; o >>= 1) s += __shfl_xor_sync(0xffffffffu, s, o);
        float r = __fdividef(1.f, s);

        float4* o4 = (float4*)(g_prob + (size_t)rowid * nc);
        cnt = 0;
        for (int j = lane; j < VL; j += 32) {
            float4 t = v[cnt++];
            t.x *= r; t.y *= r; t.z *= r; t.w *= r;
            o4[j] = t;
        }
    } else {
        float mx = -CUDART_INF_F;
        for (int c = lane; c < nc; c += 32) mx = fmaxf(mx, __ldg(&row[c]));
        #pragma unroll
        for (int o = 16; o > 0; o >>= 1) mx = fmaxf(mx, __shfl_xor_sync(0xffffffffu, mx, o));
        float s = 0.f;
        for (int c = lane; c < nc; c += 32) s += __expf(__ldg(&row[c]) - mx);
        #pragma unroll
        for (int o = 16; o > 0; o >>= 1) s += __shfl_xor_sync(0xffffffffu, s, o);
        float r = __fdividef(1.f, s);
        for (int c = lane; c < nc; c += 32)
            g_prob[(size_t)rowid * nc + c] = __expf(__ldg(&row[c]) - mx) * r;
    }
}

// =============== kernel 2: pairwise cost =====================================
#define TPB_COST 256
#define TILE_N 16
#define MPT 2

__device__ __forceinline__ float pair_cost(
    const float4& p0, const float4& p1, const float4& p2, const float4& p3,
    float pc,
    const float4& t0, const float4& t1, const float4& t2, const float4& t3)
{
    float lox = fmaxf(p0.x, t0.x), loy = fmaxf(p0.y, t0.y), loz = fmaxf(p0.z, t0.z);
    float hix = fminf(p1.x, t1.x), hiy = fminf(p1.y, t1.y), hiz = fminf(p1.z, t1.z);
    float dx = fmaxf(hix - lox, 0.f);
    float dy = fmaxf(hiy - loy, 0.f);
    float dz = fmaxf(hiz - loz, 0.f);
    float inter = dx * dy * dz;

    float uni = p0.w + t0.w - inter;

    float elx = fminf(p0.x, t0.x), ely = fminf(p0.y, t0.y), elz = fminf(p0.z, t0.z);
    float ehx = fmaxf(p1.x, t1.x), ehy = fmaxf(p1.y, t1.y), ehz = fmaxf(p1.z, t1.z);
    float enc = (ehx - elx) * (ehy - ely) * (ehz - elz);

    float giou = __fdividef(inter, uni + EPS) - __fdividef(enc - uni, enc + EPS);

    float bb = fabsf(p2.x - t2.x) + fabsf(p2.y - t2.y)
             + fabsf(p2.z - t2.z) + fabsf(p2.w - t2.w)
             + fabsf(p3.x - t3.x) + fabsf(p3.y - t3.y);

    return bb - pc - giou;
}

__global__ __launch_bounds__(TPB_COST, 3)
void cost_kernel(float* __restrict__ out, int N, int M, int nc) {
    __shared__ float  sp[TILE_N * MAXC];    // staged prob rows
    __shared__ float4 spx[TILE_N * 4];      // staged pred ext rows

    int n0   = blockIdx.y * TILE_N;
    int nend = min(TILE_N, N - n0);
    int tid  = threadIdx.x;
    bool fits = (nc <= MAXC);

    if (fits) {
        int tot  = nend * nc;
        int tot4 = tot >> 2;
        const float4* src = (const float4*)(g_prob + (size_t)n0 * nc);
        for (int j = tid; j < tot4; j += TPB_COST)
            ((float4*)sp)[j] = __ldg(&src[j]);
        for (int j = (tot4 << 2) + tid; j < tot; j += TPB_COST)
            sp[j] = __ldg(&g_prob[(size_t)n0 * nc + j]);
    }
    for (int j = tid; j < nend * 4; j += TPB_COST)
        spx[j] = __ldg(&g_pext[(size_t)n0 * 4 + j]);
    __syncthreads();

    int m0 = (blockIdx.x * TPB_COST + tid) * MPT;
    if (m0 >= M) return;

    if (m0 + MPT <= M) {
        // 2-target path: target state lives in registers across the n-tile
        float4 a0 = g_text[m0*4+0], a1 = g_text[m0*4+1];
        float4 a2 = g_text[m0*4+2], a3 = g_text[m0*4+3];
        float4 b0 = g_text[m0*4+4], b1 = g_text[m0*4+5];
        float4 b2 = g_text[m0*4+6], b3 = g_text[m0*4+7];
        int labA = __float_as_int(a1.w);
        int labB = __float_as_int(b1.w);

        #pragma unroll 4
        for (int i = 0; i < nend; i++) {
            float4 p0 = spx[i*4+0];
            float4 p1 = spx[i*4+1];
            float4 p2 = spx[i*4+2];
            float4 p3 = spx[i*4+3];
            const float* prow = fits ? (sp + i * nc)
                                     : (g_prob + (size_t)(n0 + i) * nc);
            float pcA = fits ? prow[labA] : __ldg(&prow[labA]);
            float pcB = fits ? prow[labB] : __ldg(&prow[labB]);

            float cA = pair_cost(p0, p1, p2, p3, pcA, a0, a1, a2, a3);
            float cB = pair_cost(p0, p1, p2, p3, pcB, b0, b1, b2, b3);

            *(float2*)(out + (size_t)(n0 + i) * M + m0) = make_float2(cA, cB);
        }
    } else {
        // ragged tail: scalar per m
        for (int m = m0; m < M; m++) {
            float4 t0 = g_text[m*4+0], t1 = g_text[m*4+1];
            float4 t2 = g_text[m*4+2], t3 = g_text[m*4+3];
            int lab = __float_as_int(t1.w);
            for (int i = 0; i < nend; i++) {
                float4 p0 = spx[i*4+0], p1 = spx[i*4+1];
                float4 p2 = spx[i*4+2], p3 = spx[i*4+3];
                const float* prow = fits ? (sp + i * nc)
                                         : (g_prob + (size_t)(n0 + i) * nc);
                float pc = fits ? prow[lab] : __ldg(&prow[lab]);
                out[(size_t)(n0 + i) * M + m] =
                    pair_cost(p0, p1, p2, p3, pc, t0, t1, t2, t3);
            }
        }
    }
}

// ---------------- launch ----------------
extern "C" void kernel_launch(void* const* d_in, const int* in_sizes, int n_in,
                              void* d_out, int out_size) {
    // ---- identify inputs by element count (order-proof) ----
    int iLab = 0;
    for (int i = 1; i < n_in; i++)
        if (in_sizes[i] < in_sizes[iLab]) iLab = i;
    long long M = in_sizes[iLab];

    int iTB = -1, iTC = -1;
    for (int i = 0; i < n_in; i++) {
        if (i == iLab) continue;
        if (in_sizes[i] == 6  * M) iTB = i;
        if (in_sizes[i] == 24 * M) iTC = i;
    }
    int rem[3], r = 0;
    for (int i = 0; i < n_in; i++)
        if (i != iLab && i != iTB && i != iTC) rem[r++] = i;
    int iPB = -1, iPC = -1, iLg = -1;
    for (int a = 0; a < 3; a++) {
        for (int b = 0; b < 3; b++) {
            if (a != b && (long long)in_sizes[rem[b]] == 4LL * in_sizes[rem[a]]) {
                iPB = rem[a]; iPC = rem[b];
            }
        }
    }
    for (int a = 0; a < 3; a++)
        if (rem[a] != iPB && rem[a] != iPC) iLg = rem[a];

    const float* pred_logits  = (const float*)d_in[iLg];
    const float* pred_boxes   = (const float*)d_in[iPB];
    const float* pred_corners = (const float*)d_in[iPC];
    const void*  tgt_labels   =               d_in[iLab];
    const float* tgt_boxes    = (const float*)d_in[iTB];
    const float* tgt_corners  = (const float*)d_in[iTC];
    float* out = (float*)d_out;

    int N  = in_sizes[iPB] / 6;
    int nc = (int)((long long)in_sizes[iLg] / N);
    int Mi = (int)M;

    // launch 1: fused prep (ext blocks first, then softmax blocks)
    {
        int EB = (N + Mi + 255) / 256;
        int SB = (N + 7) / 8;
        prep_kernel<<<EB + SB, 256>>>(pred_logits, pred_boxes, pred_corners,
                                      tgt_boxes, tgt_corners, tgt_labels,
                                      N, Mi, nc, EB);
    }
    // launch 2: pairwise cost
    {
        dim3 grid((Mi + TPB_COST * MPT - 1) / (TPB_COST * MPT),
                  (N + TILE_N - 1) / TILE_N);
        cost_kernel<<<grid, TPB_COST>>>(out, N, Mi, nc);
    }
}

// round 7
// speedup vs baseline: 1.2232x; 1.0626x over previous
#include <cuda_runtime.h>
#include <math_constants.h>

// ---------------- scratch (static __device__, no allocation) ----------------
#define MAXN (16384)
#define MAXC (256)
#define MAXM (2048)

__device__ float  g_prob[MAXN * MAXC];   // softmax probabilities [N, nc]
__device__ float4 g_pext[MAXN * 4];      // per-pred:  {pmin,volp},{pmax,_},{box0-3},{box4,box5,_,_}
__device__ float4 g_text[MAXM * 4];      // per-tgt:   {tmin,volt},{tmax,label},{box0-3},{box4,box5,_,_}

#define EPS 1e-6f

// =============== kernel 1: fused prep (ext blocks + softmax blocks) =========
__global__ __launch_bounds__(256)
void prep_kernel(const float* __restrict__ logits,
                 const float* __restrict__ pboxes,
                 const float* __restrict__ pcorners,
                 const float* __restrict__ tboxes,
                 const float* __restrict__ tcorners,
                 const void*  __restrict__ labels,
                 int N, int M, int nc, int EB) {
    if ((int)blockIdx.x < EB) {
        // ---------------- extents path ----------------
        __shared__ int sh_hi_nonzero;
        if (threadIdx.x == 0) sh_hi_nonzero = 0;
        __syncthreads();
        {
            int nchk = M / 2; if (nchk > 64) nchk = 64;
            int j = threadIdx.x;
            if (j < nchk) {
                unsigned int hi = __ldg(&((const unsigned int*)labels)[2 * j + 1]);
                if (hi != 0u) sh_hi_nonzero = 1;
            }
        }
        __syncthreads();
        int is64 = (sh_hi_nonzero == 0);

        int i = blockIdx.x * blockDim.x + threadIdx.x;
        if (i >= N + M) return;

        int  isT = (i >= N);
        int  idx = isT ? (i - N) : i;
        const float* boxes   = isT ? tboxes   : pboxes;
        const float* corners = isT ? tcorners : pcorners;
        float4* ext = isT ? g_text : g_pext;

        const float4* c4 = (const float4*)(corners + (size_t)idx * 24);
        float v[24];
        #pragma unroll
        for (int k = 0; k < 6; k++) {
            float4 t = __ldg(&c4[k]);
            v[4*k+0] = t.x; v[4*k+1] = t.y; v[4*k+2] = t.z; v[4*k+3] = t.w;
        }
        float mnx = v[0], mny = v[1], mnz = v[2];
        float mxx = v[0], mxy = v[1], mxz = v[2];
        #pragma unroll
        for (int j = 1; j < 8; j++) {
            mnx = fminf(mnx, v[3*j+0]);  mxx = fmaxf(mxx, v[3*j+0]);
            mny = fminf(mny, v[3*j+1]);  mxy = fmaxf(mxy, v[3*j+1]);
            mnz = fminf(mnz, v[3*j+2]);  mxz = fmaxf(mxz, v[3*j+2]);
        }
        float vol = (mxx - mnx) * (mxy - mny) * (mxz - mnz);
        const float* b = boxes + (size_t)idx * 6;

        float lab = 0.f;
        if (isT) {
            int li;
            if (is64) li = (int)__ldg(&((const long long*)labels)[idx]);
            else      li = __ldg(&((const int*)labels)[idx]);
            lab = __int_as_float(li);
        }

        ext[idx*4+0] = make_float4(mnx, mny, mnz, vol);
        ext[idx*4+1] = make_float4(mxx, mxy, mxz, lab);
        ext[idx*4+2] = make_float4(__ldg(&b[0]), __ldg(&b[1]), __ldg(&b[2]), __ldg(&b[3]));
        ext[idx*4+3] = make_float4(__ldg(&b[4]), __ldg(&b[5]), 0.f, 0.f);
        return;
    }

    // ---------------- softmax path (one warp per row) ----------------
    int rowid = ((int)blockIdx.x - EB) * 8 + ((int)threadIdx.x >> 5);
    int lane  = threadIdx.x & 31;
    if (rowid >= N) return;
    const float* row = logits + (size_t)rowid * nc;

    if ((nc & 3) == 0 && nc <= 1024) {
        const float4* r4 = (const float4*)row;
        int VL = nc >> 2;
        float4 v[8];
        int cnt = 0;
        float mx = -CUDART_INF_F;
        for (int j = lane; j < VL; j += 32) {
            float4 t = __ldg(&r4[j]);
            v[cnt++] = t;
            mx = fmaxf(mx, fmaxf(fmaxf(t.x, t.y), fmaxf(t.z, t.w)));
        }
        #pragma unroll
        for (int o = 16; o > 0; o >>= 1) mx = fmaxf(mx, __shfl_xor_sync(0xffffffffu, mx, o));

        float s = 0.f;
        for (int k = 0; k < cnt; k++) {
            v[k].x = __expf(v[k].x - mx);
            v[k].y = __expf(v[k].y - mx);
            v[k].z = __expf(v[k].z - mx);
            v[k].w = __expf(v[k].w - mx);
            s += v[k].x + v[k].y + v[k].z + v[k].w;
        }
        #pragma unroll
        for (int o = 16; o > 0; o >>= 1) s += __shfl_xor_sync(0xffffffffu, s, o);
        float r = __fdividef(1.f, s);

        float4* o4 = (float4*)(g_prob + (size_t)rowid * nc);
        cnt = 0;
        for (int j = lane; j < VL; j += 32) {
            float4 t = v[cnt++];
            t.x *= r; t.y *= r; t.z *= r; t.w *= r;
            o4[j] = t;
        }
    } else {
        float mx = -CUDART_INF_F;
        for (int c = lane; c < nc; c += 32) mx = fmaxf(mx, __ldg(&row[c]));
        #pragma unroll
        for (int o = 16; o > 0; o >>= 1) mx = fmaxf(mx, __shfl_xor_sync(0xffffffffu, mx, o));
        float s = 0.f;
        for (int c = lane; c < nc; c += 32) s += __expf(__ldg(&row[c]) - mx);
        #pragma unroll
        for (int o = 16; o > 0; o >>= 1) s += __shfl_xor_sync(0xffffffffu, s, o);
        float r = __fdividef(1.f, s);
        for (int c = lane; c < nc; c += 32)
            g_prob[(size_t)rowid * nc + c] = __expf(__ldg(&row[c]) - mx) * r;
    }
}

// =============== kernel 2: pairwise cost =====================================
#define TPB_COST 256
#define TILE_N 16
#define MPT 2

__device__ __forceinline__ float pair_cost(
    const float4& p0, const float4& p1, const float4& p2, const float4& p3,
    float pc,
    const float4& t0, const float4& t1, const float4& t2, const float4& t3)
{
    float lox = fmaxf(p0.x, t0.x), loy = fmaxf(p0.y, t0.y), loz = fmaxf(p0.z, t0.z);
    float hix = fminf(p1.x, t1.x), hiy = fminf(p1.y, t1.y), hiz = fminf(p1.z, t1.z);
    float dx = fmaxf(hix - lox, 0.f);
    float dy = fmaxf(hiy - loy, 0.f);
    float dz = fmaxf(hiz - loz, 0.f);
    float inter = dx * dy * dz;

    float uni = p0.w + t0.w - inter;

    float elx = fminf(p0.x, t0.x), ely = fminf(p0.y, t0.y), elz = fminf(p0.z, t0.z);
    float ehx = fmaxf(p1.x, t1.x), ehy = fmaxf(p1.y, t1.y), ehz = fmaxf(p1.z, t1.z);
    float enc = (ehx - elx) * (ehy - ely) * (ehz - elz);

    float giou = __fdividef(inter, uni + EPS) - __fdividef(enc - uni, enc + EPS);

    float bb = fabsf(p2.x - t2.x) + fabsf(p2.y - t2.y)
             + fabsf(p2.z - t2.z) + fabsf(p2.w - t2.w)
             + fabsf(p3.x - t3.x) + fabsf(p3.y - t3.y);

    return bb - pc - giou;
}

__global__ __launch_bounds__(TPB_COST, 3)
void cost_kernel(float* __restrict__ out, int N, int M, int nc) {
    __shared__ float  sp[TILE_N * MAXC];    // staged prob rows
    __shared__ float4 spx[TILE_N * 4];      // staged pred ext rows

    int n0   = blockIdx.y * TILE_N;
    int nend = min(TILE_N, N - n0);
    int tid  = threadIdx.x;
    bool fits = (nc <= MAXC);

    if (fits) {
        int tot  = nend * nc;
        int tot4 = tot >> 2;
        const float4* src = (const float4*)(g_prob + (size_t)n0 * nc);
        for (int j = tid; j < tot4; j += TPB_COST)
            ((float4*)sp)[j] = __ldg(&src[j]);
        for (int j = (tot4 << 2) + tid; j < tot; j += TPB_COST)
            sp[j] = __ldg(&g_prob[(size_t)n0 * nc + j]);
    }
    for (int j = tid; j < nend * 4; j += TPB_COST)
        spx[j] = __ldg(&g_pext[(size_t)n0 * 4 + j]);
    __syncthreads();

    int m0 = (blockIdx.x * TPB_COST + tid) * MPT;
    if (m0 >= M) return;

    if (m0 + 2 <= M && nend == TILE_N && fits) {
        // ---------- specialized fast path: full unroll, pointer bumps ----------
        float4 a0 = g_text[m0*4+0], a1 = g_text[m0*4+1];
        float4 a2 = g_text[m0*4+2], a3 = g_text[m0*4+3];
        float4 b0 = g_text[m0*4+4], b1 = g_text[m0*4+5];
        float4 b2 = g_text[m0*4+6], b3 = g_text[m0*4+7];

        const float*  pA = sp + __float_as_int(a1.w);   // gather ptr, bumped by nc
        const float*  pB = sp + __float_as_int(b1.w);
        const float4* pp = spx;                         // pred-ext ptr, bumped by 4
        float*        op = out + (size_t)n0 * M + m0;   // output ptr, bumped by M

        #pragma unroll
        for (int i = 0; i < TILE_N; i++) {
            float4 p0 = pp[0];
            float4 p1 = pp[1];
            float4 p2 = pp[2];
            float4 p3 = pp[3];
            float pcA = pA[0];
            float pcB = pB[0];

            float cA = pair_cost(p0, p1, p2, p3, pcA, a0, a1, a2, a3);
            float cB = pair_cost(p0, p1, p2, p3, pcB, b0, b1, b2, b3);

            *(float2*)op = make_float2(cA, cB);
            pp += 4;
            pA += nc;
            pB += nc;
            op += M;
        }
    } else if (m0 + 2 <= M) {
        // ---------- 2-target generic path ----------
        float4 a0 = g_text[m0*4+0], a1 = g_text[m0*4+1];
        float4 a2 = g_text[m0*4+2], a3 = g_text[m0*4+3];
        float4 b0 = g_text[m0*4+4], b1 = g_text[m0*4+5];
        float4 b2 = g_text[m0*4+6], b3 = g_text[m0*4+7];
        int labA = __float_as_int(a1.w);
        int labB = __float_as_int(b1.w);

        for (int i = 0; i < nend; i++) {
            float4 p0 = spx[i*4+0], p1 = spx[i*4+1];
            float4 p2 = spx[i*4+2], p3 = spx[i*4+3];
            const float* prow = fits ? (sp + i * nc)
                                     : (g_prob + (size_t)(n0 + i) * nc);
            float pcA = fits ? prow[labA] : __ldg(&prow[labA]);
            float pcB = fits ? prow[labB] : __ldg(&prow[labB]);
            float cA = pair_cost(p0, p1, p2, p3, pcA, a0, a1, a2, a3);
            float cB = pair_cost(p0, p1, p2, p3, pcB, b0, b1, b2, b3);
            *(float2*)(out + (size_t)(n0 + i) * M + m0) = make_float2(cA, cB);
        }
    } else {
        // ---------- ragged tail: scalar per m ----------
        for (int m = m0; m < M; m++) {
            float4 t0 = g_text[m*4+0], t1 = g_text[m*4+1];
            float4 t2 = g_text[m*4+2], t3 = g_text[m*4+3];
            int lab = __float_as_int(t1.w);
            for (int i = 0; i < nend; i++) {
                float4 p0 = spx[i*4+0], p1 = spx[i*4+1];
                float4 p2 = spx[i*4+2], p3 = spx[i*4+3];
                const float* prow = fits ? (sp + i * nc)
                                         : (g_prob + (size_t)(n0 + i) * nc);
                float pc = fits ? prow[lab] : __ldg(&prow[lab]);
                out[(size_t)(n0 + i) * M + m] =
                    pair_cost(p0, p1, p2, p3, pc, t0, t1, t2, t3);
            }
        }
    }
}

// ---------------- launch ----------------
extern "C" void kernel_launch(void* const* d_in, const int* in_sizes, int n_in,
                              void* d_out, int out_size) {
    // ---- identify inputs by element count (order-proof) ----
    int iLab = 0;
    for (int i = 1; i < n_in; i++)
        if (in_sizes[i] < in_sizes[iLab]) iLab = i;
    long long M = in_sizes[iLab];

    int iTB = -1, iTC = -1;
    for (int i = 0; i < n_in; i++) {
        if (i == iLab) continue;
        if (in_sizes[i] == 6  * M) iTB = i;
        if (in_sizes[i] == 24 * M) iTC = i;
    }
    int rem[3], r = 0;
    for (int i = 0; i < n_in; i++)
        if (i != iLab && i != iTB && i != iTC) rem[r++] = i;
    int iPB = -1, iPC = -1, iLg = -1;
    for (int a = 0; a < 3; a++) {
        for (int b = 0; b < 3; b++) {
            if (a != b && (long long)in_sizes[rem[b]] == 4LL * in_sizes[rem[a]]) {
                iPB = rem[a]; iPC = rem[b];
            }
        }
    }
    for (int a = 0; a < 3; a++)
        if (rem[a] != iPB && rem[a] != iPC) iLg = rem[a];

    const float* pred_logits  = (const float*)d_in[iLg];
    const float* pred_boxes   = (const float*)d_in[iPB];
    const float* pred_corners = (const float*)d_in[iPC];
    const void*  tgt_labels   =               d_in[iLab];
    const float* tgt_boxes    = (const float*)d_in[iTB];
    const float* tgt_corners  = (const float*)d_in[iTC];
    float* out = (float*)d_out;

    int N  = in_sizes[iPB] / 6;
    int nc = (int)((long long)in_sizes[iLg] / N);
    int Mi = (int)M;

    // launch 1: fused prep (ext blocks first, then softmax blocks)
    {
        int EB = (N + Mi + 255) / 256;
        int SB = (N + 7) / 8;
        prep_kernel<<<EB + SB, 256>>>(pred_logits, pred_boxes, pred_corners,
                                      tgt_boxes, tgt_corners, tgt_labels,
                                      N, Mi, nc, EB);
    }
    // launch 2: pairwise cost
    {
        dim3 grid((Mi + TPB_COST * MPT - 1) / (TPB_COST * MPT),
                  (N + TILE_N - 1) / TILE_N);
        cost_kernel<<<grid, TPB_COST>>>(out, N, Mi, nc);
    }
}

// round 8
// speedup vs baseline: 1.3230x; 1.0816x over previous
#include <cuda_runtime.h>
#include <math_constants.h>

// ---------------- scratch (static __device__, no allocation) ----------------
#define MAXN (16384)
#define MAXC (256)
#define MAXM (2048)

__device__ float  g_prob[MAXN * MAXC];   // softmax probabilities [N, nc]
__device__ float4 g_pext[MAXN * 4];      // per-pred:  {pmin,volp},{pmax,_},{box0-3},{box4,box5,_,_}
__device__ float4 g_text[MAXM * 4];      // per-tgt:   {tmin,volt},{tmax,label},{box0-3},{box4,box5,_,_}

#define EPS 1e-6f

__device__ __forceinline__ float frcp(float x) {
    float y;
    asm("rcp.approx.f32 %0, %1;" : "=f"(y) : "f"(x));
    return y;
}

// =============== kernel 1: fused prep (ext blocks + softmax blocks) =========
__global__ __launch_bounds__(256)
void prep_kernel(const float* __restrict__ logits,
                 const float* __restrict__ pboxes,
                 const float* __restrict__ pcorners,
                 const float* __restrict__ tboxes,
                 const float* __restrict__ tcorners,
                 const void*  __restrict__ labels,
                 int N, int M, int nc, int EB) {
    if ((int)blockIdx.x < EB) {
        // ---------------- extents path ----------------
        __shared__ int sh_hi_nonzero;
        if (threadIdx.x == 0) sh_hi_nonzero = 0;
        __syncthreads();
        {
            int nchk = M / 2; if (nchk > 64) nchk = 64;
            int j = threadIdx.x;
            if (j < nchk) {
                unsigned int hi = __ldg(&((const unsigned int*)labels)[2 * j + 1]);
                if (hi != 0u) sh_hi_nonzero = 1;
            }
        }
        __syncthreads();
        int is64 = (sh_hi_nonzero == 0);

        int i = blockIdx.x * blockDim.x + threadIdx.x;
        if (i >= N + M) return;

        int  isT = (i >= N);
        int  idx = isT ? (i - N) : i;
        const float* boxes   = isT ? tboxes   : pboxes;
        const float* corners = isT ? tcorners : pcorners;
        float4* ext = isT ? g_text : g_pext;

        const float4* c4 = (const float4*)(corners + (size_t)idx * 24);
        float v[24];
        #pragma unroll
        for (int k = 0; k < 6; k++) {
            float4 t = __ldg(&c4[k]);
            v[4*k+0] = t.x; v[4*k+1] = t.y; v[4*k+2] = t.z; v[4*k+3] = t.w;
        }
        float mnx = v[0], mny = v[1], mnz = v[2];
        float mxx = v[0], mxy = v[1], mxz = v[2];
        #pragma unroll
        for (int j = 1; j < 8; j++) {
            mnx = fminf(mnx, v[3*j+0]);  mxx = fmaxf(mxx, v[3*j+0]);
            mny = fminf(mny, v[3*j+1]);  mxy = fmaxf(mxy, v[3*j+1]);
            mnz = fminf(mnz, v[3*j+2]);  mxz = fmaxf(mxz, v[3*j+2]);
        }
        float vol = (mxx - mnx) * (mxy - mny) * (mxz - mnz);
        const float* b = boxes + (size_t)idx * 6;

        float lab = 0.f;
        if (isT) {
            int li;
            if (is64) li = (int)__ldg(&((const long long*)labels)[idx]);
            else      li = __ldg(&((const int*)labels)[idx]);
            lab = __int_as_float(li);
        }

        ext[idx*4+0] = make_float4(mnx, mny, mnz, vol);
        ext[idx*4+1] = make_float4(mxx, mxy, mxz, lab);
        ext[idx*4+2] = make_float4(__ldg(&b[0]), __ldg(&b[1]), __ldg(&b[2]), __ldg(&b[3]));
        ext[idx*4+3] = make_float4(__ldg(&b[4]), __ldg(&b[5]), 0.f, 0.f);
        return;
    }

    int lane = threadIdx.x & 31;

    if (nc == 256) {
        // ---------- specialized softmax: 2 rows per warp, fully static ----------
        int w  = ((int)blockIdx.x - EB) * 8 + ((int)threadIdx.x >> 5);
        int r0 = w * 2;
        if (r0 >= N) return;
        int r1 = (r0 + 1 < N) ? (r0 + 1) : r0;

        const float4* q0 = (const float4*)(logits + (size_t)r0 * 256);
        const float4* q1 = (const float4*)(logits + (size_t)r1 * 256);

        // 64 float4 per row, 2 per lane per row -> MLP 4
        float4 a0 = __ldg(&q0[lane]);
        float4 a1 = __ldg(&q0[lane + 32]);
        float4 b0 = __ldg(&q1[lane]);
        float4 b1 = __ldg(&q1[lane + 32]);

        float mxA = fmaxf(fmaxf(fmaxf(a0.x, a0.y), fmaxf(a0.z, a0.w)),
                          fmaxf(fmaxf(a1.x, a1.y), fmaxf(a1.z, a1.w)));
        float mxB = fmaxf(fmaxf(fmaxf(b0.x, b0.y), fmaxf(b0.z, b0.w)),
                          fmaxf(fmaxf(b1.x, b1.y), fmaxf(b1.z, b1.w)));
        #pragma unroll
        for (int o = 16; o > 0; o >>= 1) {
            mxA = fmaxf(mxA, __shfl_xor_sync(0xffffffffu, mxA, o));
            mxB = fmaxf(mxB, __shfl_xor_sync(0xffffffffu, mxB, o));
        }

        a0.x = __expf(a0.x - mxA); a0.y = __expf(a0.y - mxA);
        a0.z = __expf(a0.z - mxA); a0.w = __expf(a0.w - mxA);
        a1.x = __expf(a1.x - mxA); a1.y = __expf(a1.y - mxA);
        a1.z = __expf(a1.z - mxA); a1.w = __expf(a1.w - mxA);
        b0.x = __expf(b0.x - mxB); b0.y = __expf(b0.y - mxB);
        b0.z = __expf(b0.z - mxB); b0.w = __expf(b0.w - mxB);
        b1.x = __expf(b1.x - mxB); b1.y = __expf(b1.y - mxB);
        b1.z = __expf(b1.z - mxB); b1.w = __expf(b1.w - mxB);

        float sA = (a0.x + a0.y) + (a0.z + a0.w) + (a1.x + a1.y) + (a1.z + a1.w);
        float sB = (b0.x + b0.y) + (b0.z + b0.w) + (b1.x + b1.y) + (b1.z + b1.w);
        #pragma unroll
        for (int o = 16; o > 0; o >>= 1) {
            sA += __shfl_xor_sync(0xffffffffu, sA, o);
            sB += __shfl_xor_sync(0xffffffffu, sB, o);
        }
        float rA = frcp(sA), rB = frcp(sB);

        float4* oA = (float4*)(g_prob + (size_t)r0 * 256);
        float4* oB = (float4*)(g_prob + (size_t)r1 * 256);
        a0.x *= rA; a0.y *= rA; a0.z *= rA; a0.w *= rA;
        a1.x *= rA; a1.y *= rA; a1.z *= rA; a1.w *= rA;
        b0.x *= rB; b0.y *= rB; b0.z *= rB; b0.w *= rB;
        b1.x *= rB; b1.y *= rB; b1.z *= rB; b1.w *= rB;
        oA[lane] = a0; oA[lane + 32] = a1;
        if (r1 != r0) { oB[lane] = b0; oB[lane + 32] = b1; }
        return;
    }

    // ---------- generic softmax fallback (one warp per row) ----------
    int rowid = ((int)blockIdx.x - EB) * 8 + ((int)threadIdx.x >> 5);
    if (rowid >= N) return;
    const float* row = logits + (size_t)rowid * nc;

    float mx = -CUDART_INF_F;
    for (int c = lane; c < nc; c += 32) mx = fmaxf(mx, __ldg(&row[c]));
    #pragma unroll
    for (int o = 16; o > 0; o >>= 1) mx = fmaxf(mx, __shfl_xor_sync(0xffffffffu, mx, o));
    float s = 0.f;
    for (int c = lane; c < nc; c += 32) s += __expf(__ldg(&row[c]) - mx);
    #pragma unroll
    for (int o = 16; o > 0; o >>= 1) s += __shfl_xor_sync(0xffffffffu, s, o);
    float r = __fdividef(1.f, s);
    for (int c = lane; c < nc; c += 32)
        g_prob[(size_t)rowid * nc + c] = __expf(__ldg(&row[c]) - mx) * r;
}

// =============== kernel 2: pairwise cost =====================================
#define TPB_COST 256
#define TILE_N 16
#define MPT 2

__device__ __forceinline__ float pair_cost(
    const float4& p0, const float4& p1, const float4& p2, const float4& p3,
    float pc,
    const float4& t0, const float4& t1, const float4& t2, const float4& t3)
{
    float lox = fmaxf(p0.x, t0.x), loy = fmaxf(p0.y, t0.y), loz = fmaxf(p0.z, t0.z);
    float hix = fminf(p1.x, t1.x), hiy = fminf(p1.y, t1.y), hiz = fminf(p1.z, t1.z);
    float dx = fmaxf(hix - lox, 0.f);
    float dy = fmaxf(hiy - loy, 0.f);
    float dz = fmaxf(hiz - loz, 0.f);
    float inter = (dx * dy) * dz;

    float uniE = (p0.w + t0.w) - inter + EPS;

    float elx = fminf(p0.x, t0.x), ely = fminf(p0.y, t0.y), elz = fminf(p0.z, t0.z);
    float ehx = fmaxf(p1.x, t1.x), ehy = fmaxf(p1.y, t1.y), ehz = fmaxf(p1.z, t1.z);
    float encE = fmaf((ehx - elx) * (ehy - ely), (ehz - elz), EPS);

    // giou = inter/uniE - 1 + uniE/encE  ->  one reciprocal:
    // cost = (bb - pc + 1) - (inter*encE + uniE^2) * rcp(uniE*encE)
    float den = uniE * encE;
    float num = fmaf(uniE, uniE, inter * encE);
    float r   = frcp(den);

    float bb = (fabsf(p2.x - t2.x) + fabsf(p2.y - t2.y))
             + (fabsf(p2.z - t2.z) + fabsf(p2.w - t2.w))
             + (fabsf(p3.x - t3.x) + fabsf(p3.y - t3.y));

    float base = (bb - pc) + 1.0f;
    return fmaf(-num, r, base);
}

template <int NC>
__global__ __launch_bounds__(TPB_COST, 3)
void cost_kernel(float* __restrict__ out, int N, int M, int nc_rt) {
    const int nc = NC ? NC : nc_rt;

    __shared__ float  sp[TILE_N * MAXC];    // staged prob rows
    __shared__ float4 spx[TILE_N * 4];      // staged pred ext rows

    int n0   = blockIdx.y * TILE_N;
    int nend = min(TILE_N, N - n0);
    int tid  = threadIdx.x;
    bool fits = (nc <= MAXC);

    if (fits) {
        int tot  = nend * nc;
        int tot4 = tot >> 2;
        const float4* src = (const float4*)(g_prob + (size_t)n0 * nc);
        for (int j = tid; j < tot4; j += TPB_COST)
            ((float4*)sp)[j] = __ldg(&src[j]);
        for (int j = (tot4 << 2) + tid; j < tot; j += TPB_COST)
            sp[j] = __ldg(&g_prob[(size_t)n0 * nc + j]);
    }
    for (int j = tid; j < nend * 4; j += TPB_COST)
        spx[j] = __ldg(&g_pext[(size_t)n0 * 4 + j]);
    __syncthreads();

    int m0 = (blockIdx.x * TPB_COST + tid) * MPT;
    if (m0 >= M) return;

    if (m0 + 2 <= M && nend == TILE_N && fits) {
        // ---------- fast path: full unroll, immediate smem offsets ----------
        float4 a0 = g_text[m0*4+0], a1 = g_text[m0*4+1];
        float4 a2 = g_text[m0*4+2], a3 = g_text[m0*4+3];
        float4 b0 = g_text[m0*4+4], b1 = g_text[m0*4+5];
        float4 b2 = g_text[m0*4+6], b3 = g_text[m0*4+7];

        const float* pA = sp + __float_as_int(a1.w);
        const float* pB = sp + __float_as_int(b1.w);
        float*       op = out + (size_t)n0 * M + m0;

        #pragma unroll
        for (int i = 0; i < TILE_N; i++) {
            float4 p0 = spx[i*4+0];
            float4 p1 = spx[i*4+1];
            float4 p2 = spx[i*4+2];
            float4 p3 = spx[i*4+3];
            float pcA = pA[i * nc];     // immediate offset when NC != 0
            float pcB = pB[i * nc];

            float cA = pair_cost(p0, p1, p2, p3, pcA, a0, a1, a2, a3);
            float cB = pair_cost(p0, p1, p2, p3, pcB, b0, b1, b2, b3);

            *(float2*)op = make_float2(cA, cB);
            op += M;
        }
    } else if (m0 + 2 <= M) {
        // ---------- 2-target generic path ----------
        float4 a0 = g_text[m0*4+0], a1 = g_text[m0*4+1];
        float4 a2 = g_text[m0*4+2], a3 = g_text[m0*4+3];
        float4 b0 = g_text[m0*4+4], b1 = g_text[m0*4+5];
        float4 b2 = g_text[m0*4+6], b3 = g_text[m0*4+7];
        int labA = __float_as_int(a1.w);
        int labB = __float_as_int(b1.w);

        for (int i = 0; i < nend; i++) {
            float4 p0 = spx[i*4+0], p1 = spx[i*4+1];
            float4 p2 = spx[i*4+2], p3 = spx[i*4+3];
            const float* prow = fits ? (sp + i * nc)
                                     : (g_prob + (size_t)(n0 + i) * nc);
            float pcA = fits ? prow[labA] : __ldg(&prow[labA]);
            float pcB = fits ? prow[labB] : __ldg(&prow[labB]);
            float cA = pair_cost(p0, p1, p2, p3, pcA, a0, a1, a2, a3);
            float cB = pair_cost(p0, p1, p2, p3, pcB, b0, b1, b2, b3);
            *(float2*)(out + (size_t)(n0 + i) * M + m0) = make_float2(cA, cB);
        }
    } else {
        // ---------- ragged tail: scalar per m ----------
        for (int m = m0; m < M; m++) {
            float4 t0 = g_text[m*4+0], t1 = g_text[m*4+1];
            float4 t2 = g_text[m*4+2], t3 = g_text[m*4+3];
            int lab = __float_as_int(t1.w);
            for (int i = 0; i < nend; i++) {
                float4 p0 = spx[i*4+0], p1 = spx[i*4+1];
                float4 p2 = spx[i*4+2], p3 = spx[i*4+3];
                const float* prow = fits ? (sp + i * nc)
                                         : (g_prob + (size_t)(n0 + i) * nc);
                float pc = fits ? prow[lab] : __ldg(&prow[lab]);
                out[(size_t)(n0 + i) * M + m] =
                    pair_cost(p0, p1, p2, p3, pc, t0, t1, t2, t3);
            }
        }
    }
}

// ---------------- launch ----------------
extern "C" void kernel_launch(void* const* d_in, const int* in_sizes, int n_in,
                              void* d_out, int out_size) {
    // ---- identify inputs by element count (order-proof) ----
    int iLab = 0;
    for (int i = 1; i < n_in; i++)
        if (in_sizes[i] < in_sizes[iLab]) iLab = i;
    long long M = in_sizes[iLab];

    int iTB = -1, iTC = -1;
    for (int i = 0; i < n_in; i++) {
        if (i == iLab) continue;
        if (in_sizes[i] == 6  * M) iTB = i;
        if (in_sizes[i] == 24 * M) iTC = i;
    }
    int rem[3], r = 0;
    for (int i = 0; i < n_in; i++)
        if (i != iLab && i != iTB && i != iTC) rem[r++] = i;
    int iPB = -1, iPC = -1, iLg = -1;
    for (int a = 0; a < 3; a++) {
        for (int b = 0; b < 3; b++) {
            if (a != b && (long long)in_sizes[rem[b]] == 4LL * in_sizes[rem[a]]) {
                iPB = rem[a]; iPC = rem[b];
            }
        }
    }
    for (int a = 0; a < 3; a++)
        if (rem[a] != iPB && rem[a] != iPC) iLg = rem[a];

    const float* pred_logits  = (const float*)d_in[iLg];
    const float* pred_boxes   = (const float*)d_in[iPB];
    const float* pred_corners = (const float*)d_in[iPC];
    const void*  tgt_labels   =               d_in[iLab];
    const float* tgt_boxes    = (const float*)d_in[iTB];
    const float* tgt_corners  = (const float*)d_in[iTC];
    float* out = (float*)d_out;

    int N  = in_sizes[iPB] / 6;
    int nc = (int)((long long)in_sizes[iLg] / N);
    int Mi = (int)M;

    // launch 1: fused prep (ext blocks first, then softmax blocks)
    {
        int EB = (N + Mi + 255) / 256;
        int rows_per_block = (nc == 256) ? 16 : 8;
        int SB = (N + rows_per_block - 1) / rows_per_block;
        prep_kernel<<<EB + SB, 256>>>(pred_logits, pred_boxes, pred_corners,
                                      tgt_boxes, tgt_corners, tgt_labels,
                                      N, Mi, nc, EB);
    }
    // launch 2: pairwise cost (specialized for nc=256)
    {
        dim3 grid((Mi + TPB_COST * MPT - 1) / (TPB_COST * MPT),
                  (N + TILE_N - 1) / TILE_N);
        if (nc == 256)
            cost_kernel<256><<<grid, TPB_COST>>>(out, N, Mi, nc);
        else
            cost_kernel<0><<<grid, TPB_COST>>>(out, N, Mi, nc);
    }
}

// round 9
// speedup vs baseline: 1.3469x; 1.0181x over previous
#include <cuda_runtime.h>
#include <math_constants.h>

// ---------------- scratch (static __device__, no allocation) ----------------
#define MAXN (16384)
#define MAXC (256)
#define MAXM (2048)

__device__ float  g_prob[MAXN * MAXC];   // softmax probabilities [N, nc]
__device__ float4 g_pext[MAXN * 4];      // per-pred:  {pmin,volp},{pmax,_},{box0-3},{box4,box5,_,_}
__device__ float4 g_text[MAXM * 4];      // per-tgt:   {tmin,volt},{tmax,label},{box0-3},{box4,box5,_,_}

#define EPS 1e-6f

__device__ __forceinline__ float frcp(float x) {
    float y;
    asm("rcp.approx.f32 %0, %1;" : "=f"(y) : "f"(x));
    return y;
}

// =============== kernel 1: fused prep (ext blocks + softmax blocks) =========
__global__ __launch_bounds__(256)
void prep_kernel(const float* __restrict__ logits,
                 const float* __restrict__ pboxes,
                 const float* __restrict__ pcorners,
                 const float* __restrict__ tboxes,
                 const float* __restrict__ tcorners,
                 const void*  __restrict__ labels,
                 int N, int M, int nc, int EB) {
    if ((int)blockIdx.x < EB) {
        // ---------------- extents path ----------------
        __shared__ int sh_hi_nonzero;
        if (threadIdx.x == 0) sh_hi_nonzero = 0;
        __syncthreads();
        {
            int nchk = M / 2; if (nchk > 64) nchk = 64;
            int j = threadIdx.x;
            if (j < nchk) {
                unsigned int hi = __ldg(&((const unsigned int*)labels)[2 * j + 1]);
                if (hi != 0u) sh_hi_nonzero = 1;
            }
        }
        __syncthreads();
        int is64 = (sh_hi_nonzero == 0);

        int i = blockIdx.x * blockDim.x + threadIdx.x;
        if (i >= N + M) return;

        int  isT = (i >= N);
        int  idx = isT ? (i - N) : i;
        const float* boxes   = isT ? tboxes   : pboxes;
        const float* corners = isT ? tcorners : pcorners;
        float4* ext = isT ? g_text : g_pext;

        const float4* c4 = (const float4*)(corners + (size_t)idx * 24);
        float v[24];
        #pragma unroll
        for (int k = 0; k < 6; k++) {
            float4 t = __ldg(&c4[k]);
            v[4*k+0] = t.x; v[4*k+1] = t.y; v[4*k+2] = t.z; v[4*k+3] = t.w;
        }
        float mnx = v[0], mny = v[1], mnz = v[2];
        float mxx = v[0], mxy = v[1], mxz = v[2];
        #pragma unroll
        for (int j = 1; j < 8; j++) {
            mnx = fminf(mnx, v[3*j+0]);  mxx = fmaxf(mxx, v[3*j+0]);
            mny = fminf(mny, v[3*j+1]);  mxy = fmaxf(mxy, v[3*j+1]);
            mnz = fminf(mnz, v[3*j+2]);  mxz = fmaxf(mxz, v[3*j+2]);
        }
        float vol = (mxx - mnx) * (mxy - mny) * (mxz - mnz);
        const float* b = boxes + (size_t)idx * 6;

        float lab = 0.f;
        if (isT) {
            int li;
            if (is64) li = (int)__ldg(&((const long long*)labels)[idx]);
            else      li = __ldg(&((const int*)labels)[idx]);
            lab = __int_as_float(li);
        }

        ext[idx*4+0] = make_float4(mnx, mny, mnz, vol);
        ext[idx*4+1] = make_float4(mxx, mxy, mxz, lab);
        ext[idx*4+2] = make_float4(__ldg(&b[0]), __ldg(&b[1]), __ldg(&b[2]), __ldg(&b[3]));
        ext[idx*4+3] = make_float4(__ldg(&b[4]), __ldg(&b[5]), 0.f, 0.f);
        return;
    }

    int lane = threadIdx.x & 31;

    if (nc == 256) {
        // ---------- specialized softmax: 2 rows per warp, fully static ----------
        int w  = ((int)blockIdx.x - EB) * 8 + ((int)threadIdx.x >> 5);
        int r0 = w * 2;
        if (r0 >= N) return;
        int r1 = (r0 + 1 < N) ? (r0 + 1) : r0;

        const float4* q0 = (const float4*)(logits + (size_t)r0 * 256);
        const float4* q1 = (const float4*)(logits + (size_t)r1 * 256);

        float4 a0 = __ldg(&q0[lane]);
        float4 a1 = __ldg(&q0[lane + 32]);
        float4 b0 = __ldg(&q1[lane]);
        float4 b1 = __ldg(&q1[lane + 32]);

        float mxA = fmaxf(fmaxf(fmaxf(a0.x, a0.y), fmaxf(a0.z, a0.w)),
                          fmaxf(fmaxf(a1.x, a1.y), fmaxf(a1.z, a1.w)));
        float mxB = fmaxf(fmaxf(fmaxf(b0.x, b0.y), fmaxf(b0.z, b0.w)),
                          fmaxf(fmaxf(b1.x, b1.y), fmaxf(b1.z, b1.w)));
        #pragma unroll
        for (int o = 16; o > 0; o >>= 1) {
            mxA = fmaxf(mxA, __shfl_xor_sync(0xffffffffu, mxA, o));
            mxB = fmaxf(mxB, __shfl_xor_sync(0xffffffffu, mxB, o));
        }

        a0.x = __expf(a0.x - mxA); a0.y = __expf(a0.y - mxA);
        a0.z = __expf(a0.z - mxA); a0.w = __expf(a0.w - mxA);
        a1.x = __expf(a1.x - mxA); a1.y = __expf(a1.y - mxA);
        a1.z = __expf(a1.z - mxA); a1.w = __expf(a1.w - mxA);
        b0.x = __expf(b0.x - mxB); b0.y = __expf(b0.y - mxB);
        b0.z = __expf(b0.z - mxB); b0.w = __expf(b0.w - mxB);
        b1.x = __expf(b1.x - mxB); b1.y = __expf(b1.y - mxB);
        b1.z = __expf(b1.z - mxB); b1.w = __expf(b1.w - mxB);

        float sA = (a0.x + a0.y) + (a0.z + a0.w) + (a1.x + a1.y) + (a1.z + a1.w);
        float sB = (b0.x + b0.y) + (b0.z + b0.w) + (b1.x + b1.y) + (b1.z + b1.w);
        #pragma unroll
        for (int o = 16; o > 0; o >>= 1) {
            sA += __shfl_xor_sync(0xffffffffu, sA, o);
            sB += __shfl_xor_sync(0xffffffffu, sB, o);
        }
        float rA = frcp(sA), rB = frcp(sB);

        float4* oA = (float4*)(g_prob + (size_t)r0 * 256);
        float4* oB = (float4*)(g_prob + (size_t)r1 * 256);
        a0.x *= rA; a0.y *= rA; a0.z *= rA; a0.w *= rA;
        a1.x *= rA; a1.y *= rA; a1.z *= rA; a1.w *= rA;
        b0.x *= rB; b0.y *= rB; b0.z *= rB; b0.w *= rB;
        b1.x *= rB; b1.y *= rB; b1.z *= rB; b1.w *= rB;
        oA[lane] = a0; oA[lane + 32] = a1;
        if (r1 != r0) { oB[lane] = b0; oB[lane + 32] = b1; }
        return;
    }

    // ---------- generic softmax fallback (one warp per row) ----------
    int rowid = ((int)blockIdx.x - EB) * 8 + ((int)threadIdx.x >> 5);
    if (rowid >= N) return;
    const float* row = logits + (size_t)rowid * nc;

    float mx = -CUDART_INF_F;
    for (int c = lane; c < nc; c += 32) mx = fmaxf(mx, __ldg(&row[c]));
    #pragma unroll
    for (int o = 16; o > 0; o >>= 1) mx = fmaxf(mx, __shfl_xor_sync(0xffffffffu, mx, o));
    float s = 0.f;
    for (int c = lane; c < nc; c += 32) s += __expf(__ldg(&row[c]) - mx);
    #pragma unroll
    for (int o = 16; o > 0; o >>= 1) s += __shfl_xor_sync(0xffffffffu, s, o);
    float r = __fdividef(1.f, s);
    for (int c = lane; c < nc; c += 32)
        g_prob[(size_t)rowid * nc + c] = __expf(__ldg(&row[c]) - mx) * r;
}

// =============== kernel 2: pairwise cost =====================================
#define TPB_COST 256
#define TILE_N 16
#define MPT 4

__device__ __forceinline__ float pair_cost(
    const float4& p0, const float4& p1, const float4& p2, const float4& p3,
    float pc,
    const float4& t0, const float4& t1, const float4& t2, const float4& t3)
{
    float lox = fmaxf(p0.x, t0.x), loy = fmaxf(p0.y, t0.y), loz = fmaxf(p0.z, t0.z);
    float hix = fminf(p1.x, t1.x), hiy = fminf(p1.y, t1.y), hiz = fminf(p1.z, t1.z);
    float dx = fmaxf(hix - lox, 0.f);
    float dy = fmaxf(hiy - loy, 0.f);
    float dz = fmaxf(hiz - loz, 0.f);
    float inter = (dx * dy) * dz;

    float uniE = (p0.w + t0.w) - inter + EPS;

    float elx = fminf(p0.x, t0.x), ely = fminf(p0.y, t0.y), elz = fminf(p0.z, t0.z);
    float ehx = fmaxf(p1.x, t1.x), ehy = fmaxf(p1.y, t1.y), ehz = fmaxf(p1.z, t1.z);
    float encE = fmaf((ehx - elx) * (ehy - ely), (ehz - elz), EPS);

    // giou = inter/uniE - 1 + uniE/encE  ->  one reciprocal:
    float den = uniE * encE;
    float num = fmaf(uniE, uniE, inter * encE);
    float r   = frcp(den);

    float bb = (fabsf(p2.x - t2.x) + fabsf(p2.y - t2.y))
             + (fabsf(p2.z - t2.z) + fabsf(p2.w - t2.w))
             + (fabsf(p3.x - t3.x) + fabsf(p3.y - t3.y));

    float base = (bb - pc) + 1.0f;
    return fmaf(-num, r, base);
}

template <int NC>
__global__ __launch_bounds__(TPB_COST, 2)
void cost_kernel(float* __restrict__ out, int N, int M, int nc_rt) {
    const int nc = NC ? NC : nc_rt;

    __shared__ float  sp[TILE_N * MAXC];    // staged prob rows
    __shared__ float4 spx[TILE_N * 4];      // staged pred ext rows

    int n0   = blockIdx.y * TILE_N;
    int nend = min(TILE_N, N - n0);
    int tid  = threadIdx.x;
    bool fits = (nc <= MAXC);

    if (fits) {
        int tot  = nend * nc;
        int tot4 = tot >> 2;
        const float4* src = (const float4*)(g_prob + (size_t)n0 * nc);
        for (int j = tid; j < tot4; j += TPB_COST)
            ((float4*)sp)[j] = __ldg(&src[j]);
        for (int j = (tot4 << 2) + tid; j < tot; j += TPB_COST)
            sp[j] = __ldg(&g_prob[(size_t)n0 * nc + j]);
    }
    for (int j = tid; j < nend * 4; j += TPB_COST)
        spx[j] = __ldg(&g_pext[(size_t)n0 * 4 + j]);
    __syncthreads();

    int m0 = (blockIdx.x * TPB_COST + tid) * MPT;
    if (m0 >= M) return;

    if (m0 + MPT <= M && nend == TILE_N && fits) {
        // ---------- fast path: 4 targets, full unroll, pipelined loads ----------
        float4 a0 = g_text[m0*4+0],  a1 = g_text[m0*4+1];
        float4 a2 = g_text[m0*4+2],  a3 = g_text[m0*4+3];
        float4 b0 = g_text[m0*4+4],  b1 = g_text[m0*4+5];
        float4 b2 = g_text[m0*4+6],  b3 = g_text[m0*4+7];
        float4 c0 = g_text[m0*4+8],  c1 = g_text[m0*4+9];
        float4 c2 = g_text[m0*4+10], c3 = g_text[m0*4+11];
        float4 d0 = g_text[m0*4+12], d1 = g_text[m0*4+13];
        float4 d2 = g_text[m0*4+14], d3 = g_text[m0*4+15];

        const float* pA = sp + __float_as_int(a1.w);
        const float* pB = sp + __float_as_int(b1.w);
        const float* pC = sp + __float_as_int(c1.w);
        const float* pD = sp + __float_as_int(d1.w);
        float*       op = out + (size_t)n0 * M + m0;

        // prologue loads for i=0
        float4 p0 = spx[0], p1 = spx[1], p2 = spx[2], p3 = spx[3];
        float pcA = pA[0], pcB = pB[0], pcC = pC[0], pcD = pD[0];

        #pragma unroll
        for (int i = 0; i < TILE_N; i++) {
            float4 q0, q1, q2, q3;
            float nA, nB, nC, nD;
            if (i + 1 < TILE_N) {
                q0 = spx[(i+1)*4+0]; q1 = spx[(i+1)*4+1];
                q2 = spx[(i+1)*4+2]; q3 = spx[(i+1)*4+3];
                nA = pA[(i+1) * nc]; nB = pB[(i+1) * nc];
                nC = pC[(i+1) * nc]; nD = pD[(i+1) * nc];
            }

            float cA = pair_cost(p0, p1, p2, p3, pcA, a0, a1, a2, a3);
            float cB = pair_cost(p0, p1, p2, p3, pcB, b0, b1, b2, b3);
            float cC = pair_cost(p0, p1, p2, p3, pcC, c0, c1, c2, c3);
            float cD = pair_cost(p0, p1, p2, p3, pcD, d0, d1, d2, d3);

            *(float4*)op = make_float4(cA, cB, cC, cD);
            op += M;

            if (i + 1 < TILE_N) {
                p0 = q0; p1 = q1; p2 = q2; p3 = q3;
                pcA = nA; pcB = nB; pcC = nC; pcD = nD;
            }
        }
    } else {
        // ---------- generic path: scalar per m (ragged / non-256) ----------
        for (int m = m0; m < min(m0 + MPT, M); m++) {
            float4 t0 = g_text[m*4+0], t1 = g_text[m*4+1];
            float4 t2 = g_text[m*4+2], t3 = g_text[m*4+3];
            int lab = __float_as_int(t1.w);
            for (int i = 0; i < nend; i++) {
                float4 p0 = spx[i*4+0], p1 = spx[i*4+1];
                float4 p2 = spx[i*4+2], p3 = spx[i*4+3];
                const float* prow = fits ? (sp + i * nc)
                                         : (g_prob + (size_t)(n0 + i) * nc);
                float pc = fits ? prow[lab] : __ldg(&prow[lab]);
                out[(size_t)(n0 + i) * M + m] =
                    pair_cost(p0, p1, p2, p3, pc, t0, t1, t2, t3);
            }
        }
    }
}

// ---------------- launch ----------------
extern "C" void kernel_launch(void* const* d_in, const int* in_sizes, int n_in,
                              void* d_out, int out_size) {
    // ---- identify inputs by element count (order-proof) ----
    int iLab = 0;
    for (int i = 1; i < n_in; i++)
        if (in_sizes[i] < in_sizes[iLab]) iLab = i;
    long long M = in_sizes[iLab];

    int iTB = -1, iTC = -1;
    for (int i = 0; i < n_in; i++) {
        if (i == iLab) continue;
        if (in_sizes[i] == 6  * M) iTB = i;
        if (in_sizes[i] == 24 * M) iTC = i;
    }
    int rem[3], r = 0;
    for (int i = 0; i < n_in; i++)
        if (i != iLab && i != iTB && i != iTC) rem[r++] = i;
    int iPB = -1, iPC = -1, iLg = -1;
    for (int a = 0; a < 3; a++) {
        for (int b = 0; b < 3; b++) {
            if (a != b && (long long)in_sizes[rem[b]] == 4LL * in_sizes[rem[a]]) {
                iPB = rem[a]; iPC = rem[b];
            }
        }
    }
    for (int a = 0; a < 3; a++)
        if (rem[a] != iPB && rem[a] != iPC) iLg = rem[a];

    const float* pred_logits  = (const float*)d_in[iLg];
    const float* pred_boxes   = (const float*)d_in[iPB];
    const float* pred_corners = (const float*)d_in[iPC];
    const void*  tgt_labels   =               d_in[iLab];
    const float* tgt_boxes    = (const float*)d_in[iTB];
    const float* tgt_corners  = (const float*)d_in[iTC];
    float* out = (float*)d_out;

    int N  = in_sizes[iPB] / 6;
    int nc = (int)((long long)in_sizes[iLg] / N);
    int Mi = (int)M;

    // launch 1: fused prep (ext blocks first, then softmax blocks)
    {
        int EB = (N + Mi + 255) / 256;
        int rows_per_block = (nc == 256) ? 16 : 8;
        int SB = (N + rows_per_block - 1) / rows_per_block;
        prep_kernel<<<EB + SB, 256>>>(pred_logits, pred_boxes, pred_corners,
                                      tgt_boxes, tgt_corners, tgt_labels,
                                      N, Mi, nc, EB);
    }
    // launch 2: pairwise cost (specialized for nc=256)
    {
        dim3 grid((Mi + TPB_COST * MPT - 1) / (TPB_COST * MPT),
                  (N + TILE_N - 1) / TILE_N);
        if (nc == 256)
            cost_kernel<256><<<grid, TPB_COST>>>(out, N, Mi, nc);
        else
            cost_kernel<0><<<grid, TPB_COST>>>(out, N, Mi, nc);
    }
}